// round 1
// baseline (speedup 1.0000x reference)
#include <cuda_runtime.h>

// MoEGate: x[16384,2048] fp32, W[64,2048] fp32
// logits = x @ W^T ; softmax ; top-2 ; normalized weights ; seq-aux loss
// out layout (fp32): [0,32768) indices-as-float, [32768,65536) weights, [65536] aux_loss

#define N_TOKENS 16384
#define DDIM     2048
#define NEXP     64
#define BM       64
#define BK       32
#define NCTA     (N_TOKENS / BM)   // 256
#define S_LEN    4096
#define NBATCH   4

// deterministic aux-loss partials (per-CTA), 2 * 256*64*4B = 128 KB device scratch
__device__ float g_cnt[NCTA * NEXP];
__device__ float g_sum[NCTA * NEXP];

struct SmemGemm {
    float As[2][BK][BM];   // x tile, [k][token]
    float Ws[2][BK][NEXP]; // w tile, [k][expert]
};
struct SmemEpi {
    float sc[BM][NEXP + 1]; // logits -> scores, stride 65 (conflict-free column sums)
};
union SmemU {
    SmemGemm g;
    SmemEpi  e;
};

__global__ __launch_bounds__(256, 2)
void moe_gate_kernel(const float* __restrict__ x,
                     const float* __restrict__ w,
                     float* __restrict__ out)
{
    __shared__ SmemU sm;
    __shared__ int   s_cnt[NEXP];

    const int tid = threadIdx.x;
    const int cta = blockIdx.x;
    const int m0  = cta * BM;

    const int tx = tid & 15;   // expert micro-tile
    const int ty = tid >> 4;   // token  micro-tile

    // loader coords: 512 float4 per (x|w) tile, 2 per thread
    const int lr = tid >> 3;   // 0..31 (row within half-tile)
    const int lc = tid & 7;    // float4 column 0..7

    const float4* xp = reinterpret_cast<const float4*>(x);
    const float4* wp = reinterpret_cast<const float4*>(w);
    const int D4 = DDIM / 4;

    float acc[4][4];
#pragma unroll
    for (int i = 0; i < 4; i++)
#pragma unroll
        for (int j = 0; j < 4; j++) acc[i][j] = 0.0f;

    float4 xa, xb, wa, wb;

    // ---- prologue: load k-chunk 0 ----
    {
        const int k4 = 0;
        xa = xp[(m0 + lr)      * D4 + k4 + lc];
        xb = xp[(m0 + lr + 32) * D4 + k4 + lc];
        wa = wp[(lr)      * D4 + k4 + lc];
        wb = wp[(lr + 32) * D4 + k4 + lc];
        // transpose into smem [k][m]
        sm.g.As[0][lc * 4 + 0][lr] = xa.x;  sm.g.As[0][lc * 4 + 1][lr] = xa.y;
        sm.g.As[0][lc * 4 + 2][lr] = xa.z;  sm.g.As[0][lc * 4 + 3][lr] = xa.w;
        sm.g.As[0][lc * 4 + 0][lr + 32] = xb.x;  sm.g.As[0][lc * 4 + 1][lr + 32] = xb.y;
        sm.g.As[0][lc * 4 + 2][lr + 32] = xb.z;  sm.g.As[0][lc * 4 + 3][lr + 32] = xb.w;
        sm.g.Ws[0][lc * 4 + 0][lr] = wa.x;  sm.g.Ws[0][lc * 4 + 1][lr] = wa.y;
        sm.g.Ws[0][lc * 4 + 2][lr] = wa.z;  sm.g.Ws[0][lc * 4 + 3][lr] = wa.w;
        sm.g.Ws[0][lc * 4 + 0][lr + 32] = wb.x;  sm.g.Ws[0][lc * 4 + 1][lr + 32] = wb.y;
        sm.g.Ws[0][lc * 4 + 2][lr + 32] = wb.z;  sm.g.Ws[0][lc * 4 + 3][lr + 32] = wb.w;
    }
    __syncthreads();

    const int NKT = DDIM / BK;  // 64
    for (int kt = 0; kt < NKT; kt++) {
        const int buf = kt & 1;

        if (kt + 1 < NKT) {
            const int k4 = (kt + 1) * (BK / 4);
            xa = xp[(m0 + lr)      * D4 + k4 + lc];
            xb = xp[(m0 + lr + 32) * D4 + k4 + lc];
            wa = wp[(lr)      * D4 + k4 + lc];
            wb = wp[(lr + 32) * D4 + k4 + lc];
        }

#pragma unroll
        for (int kk = 0; kk < BK; kk++) {
            float4 av = *reinterpret_cast<const float4*>(&sm.g.As[buf][kk][4 * ty]);
            float4 bv = *reinterpret_cast<const float4*>(&sm.g.Ws[buf][kk][4 * tx]);
            acc[0][0] += av.x * bv.x; acc[0][1] += av.x * bv.y;
            acc[0][2] += av.x * bv.z; acc[0][3] += av.x * bv.w;
            acc[1][0] += av.y * bv.x; acc[1][1] += av.y * bv.y;
            acc[1][2] += av.y * bv.z; acc[1][3] += av.y * bv.w;
            acc[2][0] += av.z * bv.x; acc[2][1] += av.z * bv.y;
            acc[2][2] += av.z * bv.z; acc[2][3] += av.z * bv.w;
            acc[3][0] += av.w * bv.x; acc[3][1] += av.w * bv.y;
            acc[3][2] += av.w * bv.z; acc[3][3] += av.w * bv.w;
        }

        if (kt + 1 < NKT) {
            const int nb = (kt + 1) & 1;
            sm.g.As[nb][lc * 4 + 0][lr] = xa.x;  sm.g.As[nb][lc * 4 + 1][lr] = xa.y;
            sm.g.As[nb][lc * 4 + 2][lr] = xa.z;  sm.g.As[nb][lc * 4 + 3][lr] = xa.w;
            sm.g.As[nb][lc * 4 + 0][lr + 32] = xb.x;  sm.g.As[nb][lc * 4 + 1][lr + 32] = xb.y;
            sm.g.As[nb][lc * 4 + 2][lr + 32] = xb.z;  sm.g.As[nb][lc * 4 + 3][lr + 32] = xb.w;
            sm.g.Ws[nb][lc * 4 + 0][lr] = wa.x;  sm.g.Ws[nb][lc * 4 + 1][lr] = wa.y;
            sm.g.Ws[nb][lc * 4 + 2][lr] = wa.z;  sm.g.Ws[nb][lc * 4 + 3][lr] = wa.w;
            sm.g.Ws[nb][lc * 4 + 0][lr + 32] = wb.x;  sm.g.Ws[nb][lc * 4 + 1][lr + 32] = wb.y;
            sm.g.Ws[nb][lc * 4 + 2][lr + 32] = wb.z;  sm.g.Ws[nb][lc * 4 + 3][lr + 32] = wb.w;
        }
        __syncthreads();
    }

    // ---- epilogue: logits -> smem (union reuse; safe after the final sync) ----
#pragma unroll
    for (int i = 0; i < 4; i++)
#pragma unroll
        for (int j = 0; j < 4; j++)
            sm.e.sc[4 * ty + i][4 * tx + j] = acc[i][j];
    if (tid < NEXP) s_cnt[tid] = 0;
    __syncthreads();

    if (tid < BM) {
        float* row = sm.e.sc[tid];
        // top-2 scan (jax.lax.top_k tie rule: earlier index wins on ties)
        float v1 = -3.4e38f, v2 = -3.4e38f;
        int   i1 = 0,        i2 = 0;
#pragma unroll 8
        for (int e = 0; e < NEXP; e++) {
            float l = row[e];
            if (l > v1)      { v2 = v1; i2 = i1; v1 = l; i1 = e; }
            else if (l > v2) { v2 = l;  i2 = e; }
        }
        // softmax (stable) — exp values in place
        float denom = 0.0f;
#pragma unroll 8
        for (int e = 0; e < NEXP; e++) {
            float ex = expf(row[e] - v1);
            row[e] = ex;
            denom += ex;
        }
        float inv = 1.0f / denom;
#pragma unroll 8
        for (int e = 0; e < NEXP; e++) row[e] *= inv;

        float s1 = row[i1], s2 = row[i2];
        float wsum = s1 + s2 + 1e-20f;

        const int g = m0 + tid;
        out[2 * g + 0]                     = (float)i1;
        out[2 * g + 1]                     = (float)i2;
        out[2 * N_TOKENS + 2 * g + 0]      = s1 / wsum;
        out[2 * N_TOKENS + 2 * g + 1]      = s2 / wsum;

        atomicAdd(&s_cnt[i1], 1);   // integer smem atomics: deterministic
        atomicAdd(&s_cnt[i2], 1);
    }
    __syncthreads();

    // per-CTA deterministic partials for aux loss
    if (tid < NEXP) {
        float ss = 0.0f;
#pragma unroll 8
        for (int t = 0; t < BM; t++) ss += sm.e.sc[t][tid];  // stride 65 -> conflict-free
        g_sum[cta * NEXP + tid] = ss;
        g_cnt[cta * NEXP + tid] = (float)s_cnt[tid];
    }
}

__global__ void moe_reduce_kernel(float* __restrict__ out)
{
    // 256 threads: (batch b, expert e) = (tid/64, tid%64); 64 CTAs per batch
    __shared__ float red[256];
    const int tid = threadIdx.x;
    const int b = tid >> 6;
    const int e = tid & 63;

    float cnt = 0.0f, ss = 0.0f;
    const int base = b * 64;  // first CTA of this batch
    for (int c = 0; c < 64; c++) {
        cnt += g_cnt[(base + c) * NEXP + e];
        ss  += g_sum[(base + c) * NEXP + e];
    }
    float ce = cnt / ((float)S_LEN * 2.0f / (float)NEXP);  // /128
    float ms = ss / (float)S_LEN;
    red[tid] = ce * ms;
    __syncthreads();
    for (int s = 128; s > 0; s >>= 1) {
        if (tid < s) red[tid] += red[tid + s];
        __syncthreads();
    }
    if (tid == 0)
        out[4 * N_TOKENS] = red[0] * 0.01f / (float)NBATCH;  // index 65536
}

extern "C" void kernel_launch(void* const* d_in, const int* in_sizes, int n_in,
                              void* d_out, int out_size)
{
    const float* x = (const float*)d_in[0];   // hidden_states [4,4096,2048]
    const float* w = (const float*)d_in[1];   // weight [64,2048]
    float* out = (float*)d_out;

    moe_gate_kernel<<<NCTA, 256>>>(x, w, out);
    moe_reduce_kernel<<<1, 256>>>(out);
}

// round 3
// speedup vs baseline: 2.0000x; 2.0000x over previous
#include <cuda_runtime.h>
#include <cstdint>

// ============================================================================
// MoEGate via legacy mma.sync tf32 3-pass split (sm_100-target safe)
// x[16384,2048] fp32, W[64,2048] fp32
// out fp32: [0,32768) indices, [32768,65536) weights, [65536] aux_loss
// ============================================================================

#define N_TOKENS 16384
#define DDIM     2048
#define NEXP     64
#define M_CTA    128
#define NCTA     (N_TOKENS / M_CTA)   // 128
#define NCHUNK   (DDIM / 32)          // 64 chunks of K=32
#define S_LEN    4096
#define NBATCH   4

// smem layout (dynamic):
//   xs: 2 stages x 128 rows x 36 floats (pad) = 2*18432 B
//   ws: 2 stages x 1024 float4            = 2*16384 B
#define XS_STRIDE   36
#define XS_STAGE_B  (128 * XS_STRIDE * 4)       // 18432
#define WS_STAGE_B  (1024 * 16)                 // 16384
#define WS_OFF      (2 * XS_STAGE_B)            // 36864
#define SMEM_BYTES  (WS_OFF + 2 * WS_STAGE_B)   // 69632
#define SC_STRIDE   66                          // epilogue scores stride (even)

// device scratch
__device__ float4 g_wpack[NCHUNK * 1024];       // fragment-packed W hi/lo
__device__ float  g_cnt[NCTA * NEXP];
__device__ float  g_sum[NCTA * NEXP];

// ---------------------------------------------------------------------------
__device__ __forceinline__ uint32_t smem_u32(const void* p) {
    uint32_t a;
    asm("{ .reg .u64 t; cvta.to.shared.u64 t, %1; cvt.u32.u64 %0, t; }" : "=r"(a) : "l"(p));
    return a;
}
__device__ __forceinline__ float tf32r(float f) {
    uint32_t u;
    asm("cvt.rna.tf32.f32 %0, %1;" : "=r"(u) : "f"(f));
    return __uint_as_float(u);
}

#define CP_ASYNC16(dst, src) \
    asm volatile("cp.async.cg.shared.global [%0], [%1], 16;" :: "r"(dst), "l"(src) : "memory")
#define CP_COMMIT() asm volatile("cp.async.commit_group;" ::: "memory")
#define CP_WAIT0()  asm volatile("cp.async.wait_group 0;" ::: "memory")

#define MMA_TF32(d, a, b0, b1) \
    asm volatile("mma.sync.aligned.m16n8k8.row.col.f32.tf32.tf32.f32 " \
        "{%0,%1,%2,%3}, {%4,%5,%6,%7}, {%8,%9}, {%0,%1,%2,%3};" \
        : "+f"((d)[0]), "+f"((d)[1]), "+f"((d)[2]), "+f"((d)[3]) \
        : "r"((a)[0]), "r"((a)[1]), "r"((a)[2]), "r"((a)[3]), "r"(b0), "r"(b1))

// ---------------------------------------------------------------------------
// Prep: pack W into mma-fragment order, tf32 hi/lo interleaved.
// f -> (c, nt, ks, lane); covers e = nt*8 + lane/4, k = c*32+ks*8+lane%4, k+4
// ---------------------------------------------------------------------------
__global__ void w_pack_kernel(const float* __restrict__ w)
{
    int f = blockIdx.x * blockDim.x + threadIdx.x;   // 0 .. 65535
    int lane = f & 31;
    int ks   = (f >> 5) & 3;
    int nt   = (f >> 7) & 7;
    int c    = f >> 10;
    int e = nt * 8 + (lane >> 2);
    int k = c * 32 + ks * 8 + (lane & 3);
    float v0 = w[e * DDIM + k];
    float v1 = w[e * DDIM + k + 4];
    float h0 = tf32r(v0), h1 = tf32r(v1);
    float l0 = tf32r(v0 - h0), l1 = tf32r(v1 - h1);
    g_wpack[f] = make_float4(h0, h1, l0, l1);
}

// ---------------------------------------------------------------------------
// Main fused kernel: GEMM + softmax + top-2 + aux partials
// ---------------------------------------------------------------------------
__global__ __launch_bounds__(128, 1)
void moe_gate_kernel(const float* __restrict__ x, float* __restrict__ out)
{
    extern __shared__ char smem[];
    float*  xs  = reinterpret_cast<float*>(smem);
    const uint32_t sb = smem_u32(smem);
    const int tid  = threadIdx.x;
    const int warp = tid >> 5;
    const int lane = tid & 31;
    const int m0   = blockIdx.x * M_CTA;

    __shared__ int s_cnt[NEXP];
    if (tid < NEXP) s_cnt[tid] = 0;

    float acc[2][8][4];
#pragma unroll
    for (int mt = 0; mt < 2; mt++)
#pragma unroll
        for (int nt = 0; nt < 8; nt++)
#pragma unroll
            for (int i = 0; i < 4; i++) acc[mt][nt][i] = 0.0f;

    // ---- async stage loader (16 x 16B per thread per chunk) ----
    auto stage_chunk = [&](int c) {
        const int buf = c & 1;
        const uint32_t xdst_base = sb + buf * XS_STAGE_B;
        const uint32_t wdst_base = sb + WS_OFF + buf * WS_STAGE_B;
#pragma unroll
        for (int i = 0; i < 8; i++) {
            int f = i * 128 + tid;          // 0..1023
            int row = f >> 3, q = f & 7;
            const float* src = x + (size_t)(m0 + row) * DDIM + c * 32 + q * 4;
            CP_ASYNC16(xdst_base + (uint32_t)(row * (XS_STRIDE * 4) + q * 16), src);
        }
        const float4* wsrc = g_wpack + c * 1024;
#pragma unroll
        for (int i = 0; i < 8; i++) {
            int f = i * 128 + tid;
            CP_ASYNC16(wdst_base + (uint32_t)(f * 16), wsrc + f);
        }
        CP_COMMIT();
    };

    stage_chunk(0);

    for (int c = 0; c < NCHUNK; c++) {
        CP_WAIT0();
        __syncthreads();
        if (c + 1 < NCHUNK) stage_chunk(c + 1);

        const int buf = c & 1;
        const float*  xsb = xs + buf * (XS_STAGE_B / 4);
        const float4* wsb = reinterpret_cast<const float4*>(smem + WS_OFF + buf * WS_STAGE_B);

#pragma unroll
        for (int ks = 0; ks < 4; ks++) {
            // A fragments: 2 m-tiles, split to tf32 hi/lo in registers
            uint32_t ah[2][4], al[2][4];
#pragma unroll
            for (int mt = 0; mt < 2; mt++) {
                const int r0 = warp * 32 + mt * 16 + (lane >> 2);
                const int c0 = ks * 8 + (lane & 3);
                float a0 = xsb[r0 * XS_STRIDE + c0];
                float a1 = xsb[(r0 + 8) * XS_STRIDE + c0];
                float a2 = xsb[r0 * XS_STRIDE + c0 + 4];
                float a3 = xsb[(r0 + 8) * XS_STRIDE + c0 + 4];
                float h0 = tf32r(a0), h1 = tf32r(a1), h2 = tf32r(a2), h3 = tf32r(a3);
                ah[mt][0] = __float_as_uint(h0); al[mt][0] = __float_as_uint(tf32r(a0 - h0));
                ah[mt][1] = __float_as_uint(h1); al[mt][1] = __float_as_uint(tf32r(a1 - h1));
                ah[mt][2] = __float_as_uint(h2); al[mt][2] = __float_as_uint(tf32r(a2 - h2));
                ah[mt][3] = __float_as_uint(h3); al[mt][3] = __float_as_uint(tf32r(a3 - h3));
            }
#pragma unroll
            for (int nt = 0; nt < 8; nt++) {
                float4 b = wsb[(nt * 4 + ks) * 32 + lane];   // [b0h,b1h,b0l,b1l]
                uint32_t bh0 = __float_as_uint(b.x), bh1 = __float_as_uint(b.y);
                uint32_t bl0 = __float_as_uint(b.z), bl1 = __float_as_uint(b.w);
#pragma unroll
                for (int mt = 0; mt < 2; mt++) {
                    MMA_TF32(acc[mt][nt], ah[mt], bh0, bh1);   // hi*hi
                    MMA_TF32(acc[mt][nt], ah[mt], bl0, bl1);   // hi*lo
                    MMA_TF32(acc[mt][nt], al[mt], bh0, bh1);   // lo*hi
                }
            }
        }
        __syncthreads();
    }

    // ---- dump logits to smem (reuse stage buffers), stride 66 ----
    float* sc = reinterpret_cast<float*>(smem);
#pragma unroll
    for (int mt = 0; mt < 2; mt++) {
        const int r0  = warp * 32 + mt * 16 + (lane >> 2);
        const int col = (lane & 3) * 2;
#pragma unroll
        for (int nt = 0; nt < 8; nt++) {
            const int cc = nt * 8 + col;
            *reinterpret_cast<float2*>(&sc[r0 * SC_STRIDE + cc]) =
                make_float2(acc[mt][nt][0], acc[mt][nt][1]);
            *reinterpret_cast<float2*>(&sc[(r0 + 8) * SC_STRIDE + cc]) =
                make_float2(acc[mt][nt][2], acc[mt][nt][3]);
        }
    }
    __syncthreads();

    // ---- per-token: top-2, softmax, outputs ----
    {
        const int t = tid;     // 0..127, one token per thread
        float* row = &sc[t * SC_STRIDE];
        float v1 = -3.4e38f, v2 = -3.4e38f;
        int i1 = 0, i2 = 0;
#pragma unroll 8
        for (int e = 0; e < NEXP; e++) {
            float l = row[e];
            if (l > v1)      { v2 = v1; i2 = i1; v1 = l; i1 = e; }
            else if (l > v2) { v2 = l; i2 = e; }
        }
        float denom = 0.0f;
#pragma unroll 8
        for (int e = 0; e < NEXP; e++) {
            float ex = expf(row[e] - v1);
            row[e] = ex;
            denom += ex;
        }
        const float inv = 1.0f / denom;
#pragma unroll 8
        for (int e = 0; e < NEXP; e++) row[e] *= inv;

        const float s1 = row[i1], s2 = row[i2];
        const float wsum = s1 + s2 + 1e-20f;
        const int g = m0 + t;
        out[2 * g + 0] = (float)i1;
        out[2 * g + 1] = (float)i2;
        out[2 * N_TOKENS + 2 * g + 0] = s1 / wsum;
        out[2 * N_TOKENS + 2 * g + 1] = s2 / wsum;

        atomicAdd(&s_cnt[i1], 1);
        atomicAdd(&s_cnt[i2], 1);
    }
    __syncthreads();

    // ---- per-CTA deterministic aux partials ----
    if (tid < NEXP) {
        float ss = 0.0f;
#pragma unroll 8
        for (int t = 0; t < M_CTA; t++) ss += sc[t * SC_STRIDE + tid];
        g_sum[blockIdx.x * NEXP + tid] = ss;
        g_cnt[blockIdx.x * NEXP + tid] = (float)s_cnt[tid];
    }
}

// ---------------------------------------------------------------------------
// Final aux-loss reduction (deterministic)
// ---------------------------------------------------------------------------
__global__ void moe_reduce_kernel(float* __restrict__ out)
{
    __shared__ float red[256];
    const int tid = threadIdx.x;
    const int b = tid >> 6;          // batch 0..3
    const int e = tid & 63;

    float cnt = 0.0f, ss = 0.0f;
    const int base = b * (NCTA / NBATCH);            // 32 CTAs per batch
    for (int c = 0; c < NCTA / NBATCH; c++) {
        cnt += g_cnt[(base + c) * NEXP + e];
        ss  += g_sum[(base + c) * NEXP + e];
    }
    float ce = cnt / ((float)S_LEN * 2.0f / (float)NEXP);   // /128
    float ms = ss / (float)S_LEN;
    red[tid] = ce * ms;
    __syncthreads();
    for (int s = 128; s > 0; s >>= 1) {
        if (tid < s) red[tid] += red[tid + s];
        __syncthreads();
    }
    if (tid == 0)
        out[4 * N_TOKENS] = red[0] * 0.01f / (float)NBATCH;
}

// ---------------------------------------------------------------------------
extern "C" void kernel_launch(void* const* d_in, const int* in_sizes, int n_in,
                              void* d_out, int out_size)
{
    const float* x = (const float*)d_in[0];
    const float* w = (const float*)d_in[1];
    float* out = (float*)d_out;

    cudaFuncSetAttribute(moe_gate_kernel,
                         cudaFuncAttributeMaxDynamicSharedMemorySize, SMEM_BYTES);

    w_pack_kernel<<<256, 256>>>(w);
    moe_gate_kernel<<<NCTA, 128, SMEM_BYTES>>>(x, out);
    moe_reduce_kernel<<<1, 256>>>(out);
}

// round 5
// speedup vs baseline: 2.7392x; 1.3696x over previous
#include <cuda_runtime.h>
#include <cuda_fp16.h>
#include <cstdint>

// ============================================================================
// MoEGate via mma.sync m16n8k16 fp16 2-term split (3 passes, scaled residuals)
// x[16384,2048] fp32, W[64,2048] fp32
// out fp32: [0,32768) indices, [32768,65536) weights, [65536] aux_loss
// ============================================================================

#define N_TOKENS 16384
#define DDIM     2048
#define NEXP     64
#define M_CTA    128
#define NCTA     (N_TOKENS / M_CTA)   // 128
#define NCHUNK   (DDIM / 32)          // 64 chunks of K=32
#define S_LEN    4096
#define NBATCH   4
#define RSCALE   4096.0f
#define INV_RS   (1.0f / 4096.0f)

// smem: 3 stages of [x: 128 rows x 36 floats][w: 512 uint4]
#define XS_STRIDE   36
#define XS_BYTES    (128 * XS_STRIDE * 4)     // 18432
#define WS_BYTES    (512 * 16)                // 8192
#define STG_SIZE    (XS_BYTES + WS_BYTES)     // 26624
#define NSTAGE      3
#define SMEM_BYTES  (NSTAGE * STG_SIZE)       // 79872
#define SC_STRIDE   66

// device scratch
__device__ uint4    g_wpk[NCHUNK * 512];      // fragment-packed W (h1 | h2*4096)
__device__ float    g_cnt[NCTA * NEXP];
__device__ float    g_sum[NCTA * NEXP];
__device__ unsigned g_ticket;

// ---------------------------------------------------------------------------
__device__ __forceinline__ uint32_t smem_u32(const void* p) {
    uint32_t a;
    asm("{ .reg .u64 t; cvta.to.shared.u64 t, %1; cvt.u32.u64 %0, t; }" : "=r"(a) : "l"(p));
    return a;
}
__device__ __forceinline__ uint32_t h2bits(float lo, float hi) {
    __half2 h = __halves2half2(__float2half_rn(lo), __float2half_rn(hi));
    return *reinterpret_cast<uint32_t*>(&h);
}

#define CP_ASYNC16(dst, src) \
    asm volatile("cp.async.cg.shared.global [%0], [%1], 16;" :: "r"(dst), "l"(src) : "memory")
#define CP_COMMIT()  asm volatile("cp.async.commit_group;" ::: "memory")
#define CP_WAIT(n)   asm volatile("cp.async.wait_group %0;" :: "n"(n) : "memory")

#define MMA_F16(d, a, b0, b1) \
    asm volatile("mma.sync.aligned.m16n8k16.row.col.f32.f16.f16.f32 " \
        "{%0,%1,%2,%3}, {%4,%5,%6,%7}, {%8,%9}, {%0,%1,%2,%3};" \
        : "+f"((d)[0]), "+f"((d)[1]), "+f"((d)[2]), "+f"((d)[3]) \
        : "r"((a)[0]), "r"((a)[1]), "r"((a)[2]), "r"((a)[3]), "r"(b0), "r"(b1))

// ---------------------------------------------------------------------------
// Prep: pack W into m16n8k16 B-fragment order, fp16 hi + scaled-residual lo.
// f = c*512 + nt*64 + ks*32 + lane
// e = nt*8 + lane/4, k0 = c*32 + ks*16 + (lane%4)*2
// ---------------------------------------------------------------------------
__global__ void w_pack_kernel(const float* __restrict__ w)
{
    int f = blockIdx.x * blockDim.x + threadIdx.x;   // 0..32767
    if (f == 0) g_ticket = 0;                        // reset per replay
    int lane = f & 31;
    int ks   = (f >> 5) & 1;
    int nt   = (f >> 6) & 7;
    int c    = f >> 9;
    int e  = nt * 8 + (lane >> 2);
    int k0 = c * 32 + ks * 16 + (lane & 3) * 2;

    float w00 = w[e * DDIM + k0],     w01 = w[e * DDIM + k0 + 1];
    float w08 = w[e * DDIM + k0 + 8], w09 = w[e * DDIM + k0 + 9];

    float h00 = __half2float(__float2half_rn(w00));
    float h01 = __half2float(__float2half_rn(w01));
    float h08 = __half2float(__float2half_rn(w08));
    float h09 = __half2float(__float2half_rn(w09));

    uint4 v;
    v.x = h2bits(h00, h01);                                  // b0 hi
    v.y = h2bits(h08, h09);                                  // b1 hi
    v.z = h2bits((w00 - h00) * RSCALE, (w01 - h01) * RSCALE);// b0 lo*4096
    v.w = h2bits((w08 - h08) * RSCALE, (w09 - h09) * RSCALE);// b1 lo*4096
    g_wpk[f] = v;
}

// ---------------------------------------------------------------------------
// Main fused kernel
// ---------------------------------------------------------------------------
__global__ __launch_bounds__(256, 1)
void moe_gate_kernel(const float* __restrict__ x, float* __restrict__ out)
{
    extern __shared__ char smem[];
    const uint32_t sb = smem_u32(smem);
    const int tid  = threadIdx.x;
    const int warp = tid >> 5;
    const int lane = tid & 31;
    const int m0   = blockIdx.x * M_CTA;

    __shared__ int s_cnt[NEXP];
    __shared__ int s_last;
    if (tid < NEXP) s_cnt[tid] = 0;

    float accm[8][4], accc[8][4];
#pragma unroll
    for (int nt = 0; nt < 8; nt++)
#pragma unroll
        for (int i = 0; i < 4; i++) { accm[nt][i] = 0.0f; accc[nt][i] = 0.0f; }

    auto stage = [&](int c) {
        const int s = c % NSTAGE;
        const uint32_t xd = sb + s * STG_SIZE;
        const uint32_t wd = xd + XS_BYTES;
#pragma unroll
        for (int i = 0; i < 4; i++) {
            int f = i * 256 + tid;          // 0..1023
            int row = f >> 3, q = f & 7;
            const float* src = x + (size_t)(m0 + row) * DDIM + c * 32 + q * 4;
            CP_ASYNC16(xd + (uint32_t)(row * (XS_STRIDE * 4) + q * 16), src);
        }
        const uint4* wsrc = g_wpk + c * 512;
#pragma unroll
        for (int i = 0; i < 2; i++) {
            int f = i * 256 + tid;          // 0..511
            CP_ASYNC16(wd + (uint32_t)(f * 16), wsrc + f);
        }
        CP_COMMIT();
    };

    stage(0);
    stage(1);

    const int r0 = warp * 16 + (lane >> 2);

    for (int c = 0; c < NCHUNK; c++) {
        if (c + 1 < NCHUNK) { CP_WAIT(1); } else { CP_WAIT(0); }
        __syncthreads();
        if (c + 2 < NCHUNK) stage(c + 2);

        const int s = c % NSTAGE;
        const float* xsb = reinterpret_cast<const float*>(smem + s * STG_SIZE);
        const uint4* wsb = reinterpret_cast<const uint4*>(smem + s * STG_SIZE + XS_BYTES);

#pragma unroll
        for (int ks = 0; ks < 2; ks++) {
            const int k0 = ks * 16 + (lane & 3) * 2;
            // A operands: rows r0, r0+8; cols k0..k0+1, k0+8..k0+9
            float2 x0 = *reinterpret_cast<const float2*>(&xsb[r0 * XS_STRIDE + k0]);
            float2 x1 = *reinterpret_cast<const float2*>(&xsb[(r0 + 8) * XS_STRIDE + k0]);
            float2 x2 = *reinterpret_cast<const float2*>(&xsb[r0 * XS_STRIDE + k0 + 8]);
            float2 x3 = *reinterpret_cast<const float2*>(&xsb[(r0 + 8) * XS_STRIDE + k0 + 8]);

            float h0x = __half2float(__float2half_rn(x0.x)), h0y = __half2float(__float2half_rn(x0.y));
            float h1x = __half2float(__float2half_rn(x1.x)), h1y = __half2float(__float2half_rn(x1.y));
            float h2x = __half2float(__float2half_rn(x2.x)), h2y = __half2float(__float2half_rn(x2.y));
            float h3x = __half2float(__float2half_rn(x3.x)), h3y = __half2float(__float2half_rn(x3.y));

            uint32_t ah[4], al[4];
            ah[0] = h2bits(h0x, h0y);
            ah[1] = h2bits(h1x, h1y);
            ah[2] = h2bits(h2x, h2y);
            ah[3] = h2bits(h3x, h3y);
            al[0] = h2bits((x0.x - h0x) * RSCALE, (x0.y - h0y) * RSCALE);
            al[1] = h2bits((x1.x - h1x) * RSCALE, (x1.y - h1y) * RSCALE);
            al[2] = h2bits((x2.x - h2x) * RSCALE, (x2.y - h2y) * RSCALE);
            al[3] = h2bits((x3.x - h3x) * RSCALE, (x3.y - h3y) * RSCALE);

            uint4 bq[8];
#pragma unroll
            for (int nt = 0; nt < 8; nt++)
                bq[nt] = wsb[nt * 64 + ks * 32 + lane];   // FIXED: matches pack layout

            // pass-major ordering: dependent-accumulator distance = 8 MMAs
#pragma unroll
            for (int nt = 0; nt < 8; nt++) MMA_F16(accm[nt], ah, bq[nt].x, bq[nt].y);
#pragma unroll
            for (int nt = 0; nt < 8; nt++) MMA_F16(accc[nt], ah, bq[nt].z, bq[nt].w);
#pragma unroll
            for (int nt = 0; nt < 8; nt++) MMA_F16(accc[nt], al, bq[nt].x, bq[nt].y);
        }
    }
    __syncthreads();

    // ---- combine passes, dump logits to smem (stride 66) ----
    float* sc = reinterpret_cast<float*>(smem);
    {
        const int col = (lane & 3) * 2;
#pragma unroll
        for (int nt = 0; nt < 8; nt++) {
            const int cc = nt * 8 + col;
            float l0 = accm[nt][0] + accc[nt][0] * INV_RS;
            float l1 = accm[nt][1] + accc[nt][1] * INV_RS;
            float l2 = accm[nt][2] + accc[nt][2] * INV_RS;
            float l3 = accm[nt][3] + accc[nt][3] * INV_RS;
            *reinterpret_cast<float2*>(&sc[r0 * SC_STRIDE + cc])       = make_float2(l0, l1);
            *reinterpret_cast<float2*>(&sc[(r0 + 8) * SC_STRIDE + cc]) = make_float2(l2, l3);
        }
    }
    __syncthreads();

    // ---- per-token: top-2, softmax, outputs ----
    if (tid < M_CTA) {
        float* row = &sc[tid * SC_STRIDE];
        float v1 = -3.4e38f, v2 = -3.4e38f;
        int i1 = 0, i2 = 0;
#pragma unroll 8
        for (int e = 0; e < NEXP; e++) {
            float l = row[e];
            if (l > v1)      { v2 = v1; i2 = i1; v1 = l; i1 = e; }
            else if (l > v2) { v2 = l; i2 = e; }
        }
        float denom = 0.0f;
#pragma unroll 8
        for (int e = 0; e < NEXP; e++) {
            float ex = expf(row[e] - v1);
            row[e] = ex;
            denom += ex;
        }
        const float inv = 1.0f / denom;
#pragma unroll 8
        for (int e = 0; e < NEXP; e++) row[e] *= inv;

        const float s1 = row[i1], s2 = row[i2];
        const float wsum = s1 + s2 + 1e-20f;
        const int g = m0 + tid;
        out[2 * g + 0] = (float)i1;
        out[2 * g + 1] = (float)i2;
        out[2 * N_TOKENS + 2 * g + 0] = s1 / wsum;
        out[2 * N_TOKENS + 2 * g + 1] = s2 / wsum;

        atomicAdd(&s_cnt[i1], 1);
        atomicAdd(&s_cnt[i2], 1);
    }
    __syncthreads();

    // ---- per-CTA deterministic aux partials ----
    if (tid < NEXP) {
        float ss = 0.0f;
#pragma unroll 8
        for (int t = 0; t < M_CTA; t++) ss += sc[t * SC_STRIDE + tid];
        g_sum[blockIdx.x * NEXP + tid] = ss;
        g_cnt[blockIdx.x * NEXP + tid] = (float)s_cnt[tid];
    }

    // ---- last-CTA final reduction (deterministic order) ----
    __threadfence();
    __syncthreads();
    if (tid == 0) {
        unsigned t = atomicAdd(&g_ticket, 1u);
        s_last = (t == NCTA - 1) ? 1 : 0;
    }
    __syncthreads();
    if (s_last) {
        float* red = reinterpret_cast<float*>(smem);   // reuse
        const int b = tid >> 6;          // batch 0..3
        const int e = tid & 63;
        float cnt = 0.0f, ss = 0.0f;
        const int base = b * (NCTA / NBATCH);
        for (int cc = 0; cc < NCTA / NBATCH; cc++) {
            cnt += g_cnt[(base + cc) * NEXP + e];
            ss  += g_sum[(base + cc) * NEXP + e];
        }
        float ce = cnt / ((float)S_LEN * 2.0f / (float)NEXP);
        float ms = ss / (float)S_LEN;
        red[tid] = ce * ms;
        __syncthreads();
        for (int s = 128; s > 0; s >>= 1) {
            if (tid < s) red[tid] += red[tid + s];
            __syncthreads();
        }
        if (tid == 0)
            out[4 * N_TOKENS] = red[0] * 0.01f / (float)NBATCH;
    }
}

// ---------------------------------------------------------------------------
extern "C" void kernel_launch(void* const* d_in, const int* in_sizes, int n_in,
                              void* d_out, int out_size)
{
    const float* x = (const float*)d_in[0];
    const float* w = (const float*)d_in[1];
    float* out = (float*)d_out;

    cudaFuncSetAttribute(moe_gate_kernel,
                         cudaFuncAttributeMaxDynamicSharedMemorySize, SMEM_BYTES);

    w_pack_kernel<<<128, 256>>>(w);
    moe_gate_kernel<<<NCTA, 256, SMEM_BYTES>>>(x, out);
}

// round 6
// speedup vs baseline: 2.8764x; 1.0501x over previous
#include <cuda_runtime.h>
#include <cuda_fp16.h>
#include <cstdint>

// ============================================================================
// MoEGate via mma.sync m16n8k16 fp16 2-term split (3 passes, scaled residuals)
// Round 6: M_CTA=64, grid=256, occ>=2, 4-stage cp.async (wait_group 2)
// out fp32: [0,32768) indices, [32768,65536) weights, [65536] aux_loss
// ============================================================================

#define N_TOKENS 16384
#define DDIM     2048
#define NEXP     64
#define M_CTA    64
#define NCTA     (N_TOKENS / M_CTA)   // 256
#define NCHUNK   (DDIM / 32)          // 64 chunks of K=32
#define S_LEN    4096
#define NBATCH   4
#define CTA_PER_BATCH (NCTA / NBATCH) // 64
#define RSCALE   4096.0f
#define INV_RS   (1.0f / 4096.0f)

// smem: 4 stages of [x: 64 rows x 36 floats][w: 512 uint4]
#define XS_STRIDE   36
#define XS_BYTES    (M_CTA * XS_STRIDE * 4)   // 9216
#define WS_BYTES    (512 * 16)                // 8192
#define STG_SIZE    (XS_BYTES + WS_BYTES)     // 17408
#define NSTAGE      4
#define SMEM_BYTES  (NSTAGE * STG_SIZE)       // 69632
#define SC_STRIDE   66

// device scratch
__device__ uint4    g_wpk[NCHUNK * 512];      // fragment-packed W (h1 | h2*4096)
__device__ float    g_cnt[NCTA * NEXP];
__device__ float    g_sum[NCTA * NEXP];
__device__ unsigned g_ticket;

// ---------------------------------------------------------------------------
__device__ __forceinline__ uint32_t smem_u32(const void* p) {
    uint32_t a;
    asm("{ .reg .u64 t; cvta.to.shared.u64 t, %1; cvt.u32.u64 %0, t; }" : "=r"(a) : "l"(p));
    return a;
}
__device__ __forceinline__ uint32_t pack_h2(float2 v) {
    __half2 h = __float22half2_rn(v);                 // single cvt.rn.f16x2.f32
    return *reinterpret_cast<uint32_t*>(&h);
}
__device__ __forceinline__ uint32_t h2bits(float lo, float hi) {
    __half2 h = __halves2half2(__float2half_rn(lo), __float2half_rn(hi));
    return *reinterpret_cast<uint32_t*>(&h);
}

#define CP_ASYNC16(dst, src) \
    asm volatile("cp.async.cg.shared.global [%0], [%1], 16;" :: "r"(dst), "l"(src) : "memory")
#define CP_COMMIT()  asm volatile("cp.async.commit_group;" ::: "memory")
#define CP_WAIT(n)   asm volatile("cp.async.wait_group %0;" :: "n"(n) : "memory")

#define MMA_F16(d, a, b0, b1) \
    asm volatile("mma.sync.aligned.m16n8k16.row.col.f32.f16.f16.f32 " \
        "{%0,%1,%2,%3}, {%4,%5,%6,%7}, {%8,%9}, {%0,%1,%2,%3};" \
        : "+f"((d)[0]), "+f"((d)[1]), "+f"((d)[2]), "+f"((d)[3]) \
        : "r"((a)[0]), "r"((a)[1]), "r"((a)[2]), "r"((a)[3]), "r"(b0), "r"(b1))

// ---------------------------------------------------------------------------
// Prep: pack W into m16n8k16 B-fragment order, fp16 hi + scaled-residual lo.
// f = c*512 + nt*64 + ks*32 + lane
// e = nt*8 + lane/4, k0 = c*32 + ks*16 + (lane%4)*2
// ---------------------------------------------------------------------------
__global__ void w_pack_kernel(const float* __restrict__ w)
{
    int f = blockIdx.x * blockDim.x + threadIdx.x;   // 0..32767
    if (f == 0) g_ticket = 0;                        // reset per replay
    int lane = f & 31;
    int ks   = (f >> 5) & 1;
    int nt   = (f >> 6) & 7;
    int c    = f >> 9;
    int e  = nt * 8 + (lane >> 2);
    int k0 = c * 32 + ks * 16 + (lane & 3) * 2;

    float w00 = w[e * DDIM + k0],     w01 = w[e * DDIM + k0 + 1];
    float w08 = w[e * DDIM + k0 + 8], w09 = w[e * DDIM + k0 + 9];

    float h00 = __half2float(__float2half_rn(w00));
    float h01 = __half2float(__float2half_rn(w01));
    float h08 = __half2float(__float2half_rn(w08));
    float h09 = __half2float(__float2half_rn(w09));

    uint4 v;
    v.x = h2bits(h00, h01);                                   // b0 hi
    v.y = h2bits(h08, h09);                                   // b1 hi
    v.z = h2bits((w00 - h00) * RSCALE, (w01 - h01) * RSCALE); // b0 lo*4096
    v.w = h2bits((w08 - h08) * RSCALE, (w09 - h09) * RSCALE); // b1 lo*4096
    g_wpk[f] = v;
}

// ---------------------------------------------------------------------------
// Main fused kernel
// ---------------------------------------------------------------------------
__global__ __launch_bounds__(128, 3)
void moe_gate_kernel(const float* __restrict__ x, float* __restrict__ out)
{
    extern __shared__ char smem[];
    const uint32_t sb = smem_u32(smem);
    const int tid  = threadIdx.x;
    const int warp = tid >> 5;
    const int lane = tid & 31;
    const int m0   = blockIdx.x * M_CTA;

    __shared__ int s_cnt[NEXP];
    __shared__ int s_last;
    if (tid < NEXP) s_cnt[tid] = 0;

    float accm[8][4], accc[8][4];
#pragma unroll
    for (int nt = 0; nt < 8; nt++)
#pragma unroll
        for (int i = 0; i < 4; i++) { accm[nt][i] = 0.0f; accc[nt][i] = 0.0f; }

    auto stage = [&](int c) {
        const int s = c & (NSTAGE - 1);
        const uint32_t xd = sb + s * STG_SIZE;
        const uint32_t wd = xd + XS_BYTES;
#pragma unroll
        for (int i = 0; i < 4; i++) {           // x: 512 float4
            int f = i * 128 + tid;
            int row = f >> 3, q = f & 7;
            const float* src = x + (size_t)(m0 + row) * DDIM + c * 32 + q * 4;
            CP_ASYNC16(xd + (uint32_t)(row * (XS_STRIDE * 4) + q * 16), src);
        }
        const uint4* wsrc = g_wpk + c * 512;
#pragma unroll
        for (int i = 0; i < 4; i++) {           // w: 512 uint4
            int f = i * 128 + tid;
            CP_ASYNC16(wd + (uint32_t)(f * 16), wsrc + f);
        }
        CP_COMMIT();
    };

    stage(0); stage(1); stage(2);

    const int r0 = warp * 16 + (lane >> 2);

    for (int c = 0; c < NCHUNK; c++) {
        if      (c <  NCHUNK - 2) { CP_WAIT(2); }
        else if (c == NCHUNK - 2) { CP_WAIT(1); }
        else                      { CP_WAIT(0); }
        __syncthreads();
        if (c + 3 < NCHUNK) stage(c + 3);

        const int s = c & (NSTAGE - 1);
        const float* xsb = reinterpret_cast<const float*>(smem + s * STG_SIZE);
        const uint4* wsb = reinterpret_cast<const uint4*>(smem + s * STG_SIZE + XS_BYTES);

#pragma unroll
        for (int ks = 0; ks < 2; ks++) {
            const int k0 = ks * 16 + (lane & 3) * 2;
            float2 x0 = *reinterpret_cast<const float2*>(&xsb[r0 * XS_STRIDE + k0]);
            float2 x1 = *reinterpret_cast<const float2*>(&xsb[(r0 + 8) * XS_STRIDE + k0]);
            float2 x2 = *reinterpret_cast<const float2*>(&xsb[r0 * XS_STRIDE + k0 + 8]);
            float2 x3 = *reinterpret_cast<const float2*>(&xsb[(r0 + 8) * XS_STRIDE + k0 + 8]);

            uint32_t ah[4], al[4];
            ah[0] = pack_h2(x0); ah[1] = pack_h2(x1);
            ah[2] = pack_h2(x2); ah[3] = pack_h2(x3);
            {
                __half2 h0 = *reinterpret_cast<__half2*>(&ah[0]);
                __half2 h1 = *reinterpret_cast<__half2*>(&ah[1]);
                __half2 h2 = *reinterpret_cast<__half2*>(&ah[2]);
                __half2 h3 = *reinterpret_cast<__half2*>(&ah[3]);
                al[0] = pack_h2(make_float2((x0.x - __low2float(h0)) * RSCALE,
                                            (x0.y - __high2float(h0)) * RSCALE));
                al[1] = pack_h2(make_float2((x1.x - __low2float(h1)) * RSCALE,
                                            (x1.y - __high2float(h1)) * RSCALE));
                al[2] = pack_h2(make_float2((x2.x - __low2float(h2)) * RSCALE,
                                            (x2.y - __high2float(h2)) * RSCALE));
                al[3] = pack_h2(make_float2((x3.x - __low2float(h3)) * RSCALE,
                                            (x3.y - __high2float(h3)) * RSCALE));
            }

            uint4 bq[8];
#pragma unroll
            for (int nt = 0; nt < 8; nt++)
                bq[nt] = wsb[nt * 64 + ks * 32 + lane];

            // pass-major ordering: dependent-accumulator distance = 8 MMAs
#pragma unroll
            for (int nt = 0; nt < 8; nt++) MMA_F16(accm[nt], ah, bq[nt].x, bq[nt].y);
#pragma unroll
            for (int nt = 0; nt < 8; nt++) MMA_F16(accc[nt], ah, bq[nt].z, bq[nt].w);
#pragma unroll
            for (int nt = 0; nt < 8; nt++) MMA_F16(accc[nt], al, bq[nt].x, bq[nt].y);
        }
    }
    __syncthreads();

    // ---- combine passes, dump logits to smem (stride 66) ----
    float* sc = reinterpret_cast<float*>(smem);
    {
        const int col = (lane & 3) * 2;
#pragma unroll
        for (int nt = 0; nt < 8; nt++) {
            const int cc = nt * 8 + col;
            float l0 = accm[nt][0] + accc[nt][0] * INV_RS;
            float l1 = accm[nt][1] + accc[nt][1] * INV_RS;
            float l2 = accm[nt][2] + accc[nt][2] * INV_RS;
            float l3 = accm[nt][3] + accc[nt][3] * INV_RS;
            *reinterpret_cast<float2*>(&sc[r0 * SC_STRIDE + cc])       = make_float2(l0, l1);
            *reinterpret_cast<float2*>(&sc[(r0 + 8) * SC_STRIDE + cc]) = make_float2(l2, l3);
        }
    }
    __syncthreads();

    // ---- per-token: top-2, softmax, outputs ----
    if (tid < M_CTA) {
        float* row = &sc[tid * SC_STRIDE];
        float v1 = -3.4e38f, v2 = -3.4e38f;
        int i1 = 0, i2 = 0;
#pragma unroll 8
        for (int e = 0; e < NEXP; e++) {
            float l = row[e];
            if (l > v1)      { v2 = v1; i2 = i1; v1 = l; i1 = e; }
            else if (l > v2) { v2 = l; i2 = e; }
        }
        float denom = 0.0f;
#pragma unroll 8
        for (int e = 0; e < NEXP; e++) {
            float ex = expf(row[e] - v1);
            row[e] = ex;
            denom += ex;
        }
        const float inv = 1.0f / denom;
#pragma unroll 8
        for (int e = 0; e < NEXP; e++) row[e] *= inv;

        const float s1 = row[i1], s2 = row[i2];
        const float wsum = s1 + s2 + 1e-20f;
        const int g = m0 + tid;
        out[2 * g + 0] = (float)i1;
        out[2 * g + 1] = (float)i2;
        out[2 * N_TOKENS + 2 * g + 0] = s1 / wsum;
        out[2 * N_TOKENS + 2 * g + 1] = s2 / wsum;

        atomicAdd(&s_cnt[i1], 1);
        atomicAdd(&s_cnt[i2], 1);
    }
    __syncthreads();

    // ---- per-CTA deterministic aux partials ----
    if (tid < NEXP) {
        float ss = 0.0f;
#pragma unroll 8
        for (int t = 0; t < M_CTA; t++) ss += sc[t * SC_STRIDE + tid];
        g_sum[blockIdx.x * NEXP + tid] = ss;
        g_cnt[blockIdx.x * NEXP + tid] = (float)s_cnt[tid];
    }

    // ---- last-CTA final reduction (deterministic order) ----
    __threadfence();
    __syncthreads();
    if (tid == 0) {
        unsigned t = atomicAdd(&g_ticket, 1u);
        s_last = (t == NCTA - 1) ? 1 : 0;
    }
    __syncthreads();
    if (s_last) {
        float* red = reinterpret_cast<float*>(smem);   // reuse
        const int e  = tid & 63;
        const int bh = tid >> 6;         // 0 or 1; thread covers batches bh, bh+2
        float total = 0.0f;
#pragma unroll
        for (int bi = 0; bi < 2; bi++) {
            const int b = bh + bi * 2;
            float cnt = 0.0f, ss = 0.0f;
            const int base = b * CTA_PER_BATCH;
            for (int cc = 0; cc < CTA_PER_BATCH; cc++) {
                cnt += g_cnt[(base + cc) * NEXP + e];
                ss  += g_sum[(base + cc) * NEXP + e];
            }
            float ce = cnt / ((float)S_LEN * 2.0f / (float)NEXP);
            float ms = ss / (float)S_LEN;
            total += ce * ms;
        }
        red[tid] = total;
        __syncthreads();
        for (int s = 64; s > 0; s >>= 1) {
            if (tid < s) red[tid] += red[tid + s];
            __syncthreads();
        }
        if (tid == 0)
            out[4 * N_TOKENS] = red[0] * 0.01f / (float)NBATCH;
    }
}

// ---------------------------------------------------------------------------
extern "C" void kernel_launch(void* const* d_in, const int* in_sizes, int n_in,
                              void* d_out, int out_size)
{
    const float* x = (const float*)d_in[0];
    const float* w = (const float*)d_in[1];
    float* out = (float*)d_out;

    cudaFuncSetAttribute(moe_gate_kernel,
                         cudaFuncAttributeMaxDynamicSharedMemorySize, SMEM_BYTES);

    w_pack_kernel<<<128, 256>>>(w);
    moe_gate_kernel<<<NCTA, 128, SMEM_BYTES>>>(x, out);
}